// round 12
// baseline (speedup 1.0000x reference)
#include <cuda_runtime.h>

// ---------------------------------------------------------------------------
// FFTDiffuseBase: guide (2,3,512,512) f32, initial (2,1,512,512) f32
//                 -> out (2,1,512,512) f32
//
// Phases:
//  1) cv/ch conductance maps + ur uniform-region mask
//  2) shift = (min(initial) <= 0.1) ? 0.1 : 0 ; depth = initial + shift
//  3) FFT block diffusion == 10 circular 5-pt stencil steps per 128x128 tile
//     (operator symbol is real & separable in cos ky / cos kx), executed in
//     13 dependency-correct wavefronts (w = 2i + j; same-wave tiles disjoint)
//  4) 250 diffusion iterations; dv AND dh both read the step-start field, so
//     each iteration is ONE 5-pt stencil. Fused 6 iters/kernel via halo tiles
//     (41 x 6 + 1 x 4 = 250, 42 launches). 1024 threads/CTA, per-thread
//     register-resident flux coefficients (pre-scaled by L, zeroed where the
//     flux doesn't exist -> bit-identical to the guarded form).
//  5) out = depth - shift, FUSED into the final phase-4 launch (the 8x8x2
//     grid covers the image exactly once; shift is re-derived from g_minbits).
// ---------------------------------------------------------------------------

#define IMN   (512*512)
#define CVN   (511*512)
#define CHN   (512*511)
#define URN   (511*511)
#define NB    2
#define LDIFF 0.24f

__device__ float         g_cv[NB*CVN];
__device__ float         g_ch[NB*CHN];
__device__ unsigned char g_ur[NB*URN];
__device__ float         g_depth [NB*IMN];
__device__ float         g_depth2[NB*IMN];
__device__ float         g_scrA[6*16384];
__device__ float         g_scrB[6*16384];
__device__ int           g_minbits;

// ---------------------------------------------------------------- phase 1 ---
__global__ void k_cvch(const float* __restrict__ G)
{
    int idx = blockIdx.x*blockDim.x + threadIdx.x;
    if (idx == 0) g_minbits = 0x7f800000;              // reset per replay
    if (idx >= NB*IMN) return;
    int b = idx >> 18;
    int r = idx & (IMN-1);
    int y = r >> 9;
    int x = r & 511;
    const float* Gb = G + b*3*IMN + y*512 + x;
    float a0 = Gb[0], a1 = Gb[IMN], a2 = Gb[2*IMN];
    const float inv3  = 1.0f/3.0f;
    const float invKK = 1.0f/(0.03f*0.03f);
    if (y < 511) {
        float m = (fabsf(Gb[512]-a0) + fabsf(Gb[IMN+512]-a1) + fabsf(Gb[2*IMN+512]-a2)) * inv3;
        g_cv[b*CVN + y*512 + x] = 1.0f/(1.0f + m*m*invKK);
    }
    if (x < 511) {
        float m = (fabsf(Gb[1]-a0) + fabsf(Gb[IMN+1]-a1) + fabsf(Gb[2*IMN+1]-a2)) * inv3;
        g_ch[b*CHN + y*511 + x] = 1.0f/(1.0f + m*m*invKK);
    }
}

__global__ void k_ur()
{
    int idx = blockIdx.x*blockDim.x + threadIdx.x;
    if (idx >= NB*URN) return;
    int b = idx / URN;
    int r = idx - b*URN;
    int y = r / 511;
    int x = r - y*511;
    const float* cvb = g_cv + b*CVN;
    const float* chb = g_ch + b*CHN;
    float s1=0.f, s2=0.f, t1=0.f, t2=0.f;
    #pragma unroll
    for (int dy=-1; dy<=1; ++dy) {
        int yy = y + dy;
        #pragma unroll
        for (int dx=-1; dx<=1; ++dx) {
            int xx = x + dx;
            if (yy >= 0 && yy < 511 && xx >= 0 && xx < 512) {
                float v = cvb[yy*512 + xx]; s1 += v; s2 += v*v;
            }
            if (yy >= 0 && yy < 512 && xx >= 0 && xx < 511) {
                float v = chb[yy*511 + xx]; t1 += v; t2 += v*v;
            }
        }
    }
    const float i9 = 1.0f/9.0f;
    float av = s1*i9, av2 = s2*i9;
    float bv = t1*i9, bv2 = t2*i9;
    g_ur[idx] = ((av2 - av*av) < 0.1f && (bv2 - bv*bv) < 0.1f) ? 1 : 0;
}

// ---------------------------------------------------------------- phase 2 ---
__global__ void k_min(const float* __restrict__ I)
{
    __shared__ float sm[32];
    int tid    = blockIdx.x*blockDim.x + threadIdx.x;
    int stride = gridDim.x*blockDim.x;
    float m = 3.4e38f;
    for (int i = tid; i < NB*IMN; i += stride) m = fminf(m, I[i]);
    for (int o = 16; o; o >>= 1) m = fminf(m, __shfl_down_sync(0xffffffffu, m, o));
    if ((threadIdx.x & 31) == 0) sm[threadIdx.x >> 5] = m;
    __syncthreads();
    if (threadIdx.x < 32) {
        m = (threadIdx.x < (blockDim.x >> 5)) ? sm[threadIdx.x] : 3.4e38f;
        for (int o = 16; o; o >>= 1) m = fminf(m, __shfl_down_sync(0xffffffffu, m, o));
        if (threadIdx.x == 0) atomicMin(&g_minbits, __float_as_int(m)); // inputs >= 0
    }
}

__global__ void k_seed(const float* __restrict__ I)
{
    int idx = blockIdx.x*blockDim.x + threadIdx.x;
    if (idx >= NB*IMN) return;
    float mn = __int_as_float(g_minbits);
    float sh = (mn <= 0.1f) ? 0.1f : 0.0f;
    g_depth[idx] = I[idx] + sh;
}

// ---------------------------------------------------------------- phase 3 ---
// One CTA per (batch, tile). Wave w = 2i + j: all earlier-order overlapping
// tiles have smaller wave; same-wave tiles are spatially disjoint.
__global__ void __launch_bounds__(1024) k_fft(int w, int i0)
{
    __shared__ float red[96];
    __shared__ float coef[4];

    int b  = blockIdx.x & 1;
    int t  = blockIdx.x >> 1;
    int i  = i0 + t;
    int j  = w - 2*i;
    int ty = 112*i, tx = 112*j;
    int h  = min(128, 512 - ty);
    int ww = min(128, 512 - tx);
    int tid = threadIdx.x;

    const float*         cvb = g_cv + b*CVN;
    const float*         chb = g_ch + b*CHN;
    const unsigned char* urb = g_ur + b*URN;
    float*               Db  = g_depth + b*IMN;

    // block means over reference slice shapes
    float s_cv = 0.f, s_ch = 0.f, s_ur = 0.f;
    int rh = h - 1;
    for (int k = tid; k < rh*ww; k += 1024) {
        int r = k / ww, c = k - r*ww;
        s_cv += cvb[(ty + r)*512 + tx + c];
    }
    int cw = ww - 1;
    for (int k = tid; k < h*cw; k += 1024) {
        int r = k / cw, c = k - r*cw;
        s_ch += chb[(ty + r)*511 + tx + c];
    }
    int uh = min(ty + h, 511) - ty;
    int uw = min(tx + ww, 511) - tx;
    for (int k = tid; k < uh*uw; k += 1024) {
        int r = k / uw, c = k - r*uw;
        s_ur += (float)urb[(ty + r)*511 + tx + c];
    }
    unsigned lane = tid & 31, wi = tid >> 5;
    for (int o = 16; o; o >>= 1) {
        s_cv += __shfl_down_sync(0xffffffffu, s_cv, o);
        s_ch += __shfl_down_sync(0xffffffffu, s_ch, o);
        s_ur += __shfl_down_sync(0xffffffffu, s_ur, o);
    }
    if (lane == 0) { red[wi] = s_cv; red[32+wi] = s_ch; red[64+wi] = s_ur; }
    __syncthreads();
    if (tid == 0) {
        float a = 0.f, bb = 0.f, u = 0.f;
        for (int k = 0; k < 32; ++k) { a += red[k]; bb += red[32+k]; u += red[64+k]; }
        float cvm  = a  / (float)(rh*ww);
        float chm  = bb / (float)(h*cw);
        float unif = u  / (float)(uh*uw);
        float A = LDIFF*cvm, B = LDIFF*chm;
        coef[0] = 1.0f - 2.0f*A - 2.0f*B;
        coef[1] = A; coef[2] = B; coef[3] = unif;
    }
    __syncthreads();
    float c0 = coef[0], A = coef[1], B = coef[2];
    bool  doit = coef[3] > 0.7f;

    // load tile into per-CTA scratch (row stride 128)
    float* bufA = g_scrA + blockIdx.x*16384;
    float* bufB = g_scrB + blockIdx.x*16384;
    int wsh = (ww == 128) ? 7 : 6;
    int npts = h*ww;
    for (int k = tid; k < npts; k += 1024) {
        int r = k >> wsh, c = k & (ww-1);
        bufA[(r<<7) + c] = Db[(ty + r)*512 + tx + c];
    }
    __syncthreads();

    // 10 circular 5-pt stencil steps == irfft2(rfft2(x) * op^10)
    float* src = bufA;
    float* dst = bufB;
    int qs = (ww == 128) ? 5 : 4;       // log2(ww/4)
    int wq = ww >> 2;
    int npts4 = h * wq;
    for (int it = 0; it < 10; ++it) {
        for (int k = tid; k < npts4; k += 1024) {
            int r  = k >> qs;
            int c4 = (k & (wq-1)) << 2;
            int ru = (r == 0)    ? h-1 : r-1;
            int rd = (r == h-1)  ? 0   : r+1;
            float4 ce = *(const float4*)(src + (r <<7) + c4);
            float4 up = *(const float4*)(src + (ru<<7) + c4);
            float4 dn = *(const float4*)(src + (rd<<7) + c4);
            float  lf = src[(r<<7) + ((c4 == 0)      ? ww-1 : c4-1)];
            float  rt = src[(r<<7) + ((c4 + 4 == ww) ? 0    : c4+4)];
            float4 o;
            o.x = c0*ce.x + A*(up.x + dn.x) + B*(lf   + ce.y);
            o.y = c0*ce.y + A*(up.y + dn.y) + B*(ce.x + ce.z);
            o.z = c0*ce.z + A*(up.z + dn.z) + B*(ce.y + ce.w);
            o.w = c0*ce.w + A*(up.w + dn.w) + B*(ce.z + rt);
            *(float4*)(dst + (r<<7) + c4) = o;
        }
        __syncthreads();
        float* tmp = src; src = dst; dst = tmp;
    }

    // blend + conditional commit
    for (int k = tid; k < npts; k += 1024) {
        int r = k >> wsh, c = k & (ww-1);
        int gi = (ty + r)*512 + tx + c;
        float oldv = Db[gi];
        float newv = src[(r<<7) + c];
        float by = (ty > 0 && r < 16) ? (float)r * (1.0f/16.0f) : 1.0f;
        float bx = (tx > 0 && c < 16) ? (float)c * (1.0f/16.0f) : 1.0f;
        float bl = by * bx;
        float cand = oldv*(1.0f - bl) + newv*bl;
        Db[gi] = doit ? cand : oldv;
    }
}

// ---------------------------------------------------------------- phase 4 ---
// Up to 6 fused stencil iterations per launch. 64x64 output tile, 76x76 halo
// tile in smem ping-pong (2 x 76 x 78 x 4 = 47.4 KB static smem).
// Fixed per-thread ownership of <=6 points; the 4 flux coefficients are
// preloaded into registers ONCE (pre-scaled by L; zeroed where the flux does
// not exist -> reproduces the guarded arithmetic exactly). Iteration `it`
// writes only [it+1, HT-2-it]^2 — the exact region iteration it+1 reads.
// On the final launch (fout != nullptr) the epilogue writes out = v - shift
// directly, fusing the former k_final pass.
#define FUSE 6
#define TS   64
#define HT   (TS + 2*FUSE)   // 76
#define PADW (HT + 2)        // 78
#define NTH  1024
#define NPT  ((HT*HT + NTH - 1)/NTH)   // 6

__global__ void __launch_bounds__(NTH) k_iter(int parity, int niter, float* fout)
{
    const float* I = (parity ? g_depth2 : g_depth)  + blockIdx.z*IMN;
    float*       O = (parity ? g_depth  : g_depth2) + blockIdx.z*IMN;
    const float* cvb = g_cv + blockIdx.z*CVN;
    const float* chb = g_ch + blockIdx.z*CHN;
    int y0 = blockIdx.y*TS - FUSE;
    int x0 = blockIdx.x*TS - FUSE;

    __shared__ float sA[HT*PADW];
    __shared__ float sB[HT*PADW];
    int tid = threadIdx.x;

    // preload field into smem + flux coefficients into registers
    float cvd[NPT], cvu[NPT], chr[NPT], chl[NPT];
    #pragma unroll
    for (int i = 0; i < NPT; ++i) {
        int k = tid + i*NTH;
        float a = 0.f, b = 0.f, cR = 0.f, cL = 0.f;
        if (k < HT*HT) {
            int r = k / HT, c = k - (k / HT)*HT;
            int y = y0 + r, x = x0 + c;
            float v = 0.0f;
            if ((unsigned)y < 512u && (unsigned)x < 512u) {
                v = I[y*512 + x];
                if (y < 511) a  = LDIFF * cvb[y*512 + x];
                if (y > 0)   b  = LDIFF * cvb[(y-1)*512 + x];
                if (x < 511) cR = LDIFF * chb[y*511 + x];
                if (x > 0)   cL = LDIFF * chb[y*511 + x - 1];
            }
            sA[r*PADW + c] = v;
        }
        cvd[i] = a; cvu[i] = b; chr[i] = cR; chl[i] = cL;
    }
    __syncthreads();

    float* src = sA;
    float* dst = sB;
    #pragma unroll 1
    for (int it = 0; it < niter; ++it) {
        int lo = it + 1;
        int hi = HT - 2 - it;
        #pragma unroll
        for (int i = 0; i < NPT; ++i) {
            int k = tid + i*NTH;
            int r = k / HT, c = k - (k / HT)*HT;    // HT constant -> mul/shift
            if (k < HT*HT && r >= lo && r <= hi && c >= lo && c <= hi) {
                float cen = src[r*PADW + c];
                float acc = cen
                    + cvd[i] * (src[(r+1)*PADW + c] - cen)
                    - cvu[i] * (cen - src[(r-1)*PADW + c])
                    + chr[i] * (src[r*PADW + c + 1] - cen)
                    - chl[i] * (cen - src[r*PADW + c - 1]);
                dst[r*PADW + c] = acc;
            }
        }
        __syncthreads();
        float* t = src; src = dst; dst = t;
    }

    if (fout) {
        // fused phase 5: out = depth - shift (full image covered exactly once)
        float mn = __int_as_float(g_minbits);
        float sh = (mn <= 0.1f) ? 0.1f : 0.0f;
        float* Fb = fout + blockIdx.z*IMN;
        for (int k = tid; k < TS*TS; k += NTH) {
            int r = k >> 6, c = k & 63;
            int y = y0 + FUSE + r, x = x0 + FUSE + c;
            Fb[y*512 + x] = src[(r+FUSE)*PADW + (c+FUSE)] - sh;
        }
    } else {
        for (int k = tid; k < TS*TS; k += NTH) {
            int r = k >> 6, c = k & 63;
            int y = y0 + FUSE + r, x = x0 + FUSE + c;
            O[y*512 + x] = src[(r+FUSE)*PADW + (c+FUSE)];
        }
    }
}

// ---------------------------------------------------------------------------
extern "C" void kernel_launch(void* const* d_in, const int* in_sizes, int n_in,
                              void* d_out, int out_size)
{
    const float* guide   = (const float*)d_in[0];
    const float* initial = (const float*)d_in[1];
    float*       out     = (float*)d_out;

    k_cvch<<<2048, 256>>>(guide);
    k_ur  <<<(NB*URN + 255)/256, 256>>>();
    k_min <<<512, 256>>>(initial);
    k_seed<<<2048, 256>>>(initial);

    for (int w = 0; w < 13; ++w) {
        int i_min = (w - 3) / 2; if (i_min < 0) i_min = 0;
        int i_max = w / 2;       if (i_max > 4) i_max = 4;
        int nt = i_max - i_min + 1;
        k_fft<<<nt*2, 1024>>>(w, i_min);
    }

    // 41 launches x 6 iters + 1 launch x 4 iters = 250; the final launch
    // writes the shifted result straight to d_out (fused phase 5).
    for (int f = 0; f < 42; ++f)
        k_iter<<<dim3(8, 8, NB), NTH>>>(f & 1, (f < 41) ? 6 : 4,
                                        (f == 41) ? out : nullptr);
}

// round 15
// speedup vs baseline: 1.1454x; 1.1454x over previous
#include <cuda_runtime.h>

// ---------------------------------------------------------------------------
// FFTDiffuseBase: guide (2,3,512,512) f32, initial (2,1,512,512) f32
//                 -> out (2,1,512,512) f32
//
//  1) cv/ch conductance maps + ur uniform-region mask
//  2) (ELIMINATED) the +shift/-shift pair cancels by linearity: every
//     operator applied to depth is affine with unit constant response
//     (FFT op symbol at k=0 is 1; blend coefficients sum to 1; scan steps
//     add pure difference terms). diffuse(x+s)-s == diffuse(x) up to fp
//     rounding, orders of magnitude inside the 1e-3 gate.
//  3) FFT block diffusion == 10 circular 5-pt stencil steps per 128x128 tile,
//     ping-pong in 128 KB dynamic smem; 13 dependency-correct wavefronts
//     (w = 2i + j; same-wave tiles disjoint).
//  4) 250 diffusion iterations == 250 fused 5-pt stencils; FUSE=10 per launch
//     via 84x84 halo tiles in 57.8 KB dynamic smem -> exactly 25 launches.
//     Per-thread register-resident flux coefficients (zeroed where the flux
//     doesn't exist -> bit-identical to guarded arithmetic).
//  5) final launch writes the result straight to d_out.
// ---------------------------------------------------------------------------

#define IMN   (512*512)
#define CVN   (511*512)
#define CHN   (512*511)
#define URN   (511*511)
#define NB    2
#define LDIFF 0.24f

__device__ float         g_cv[NB*CVN];
__device__ float         g_ch[NB*CHN];
__device__ unsigned char g_ur[NB*URN];
__device__ float         g_depth [NB*IMN];
__device__ float         g_depth2[NB*IMN];

// ---------------------------------------------------------------- phase 1 ---
__global__ void k_cvch(const float* __restrict__ G)
{
    int idx = blockIdx.x*blockDim.x + threadIdx.x;
    if (idx >= NB*IMN) return;
    int b = idx >> 18;
    int r = idx & (IMN-1);
    int y = r >> 9;
    int x = r & 511;
    const float* Gb = G + b*3*IMN + y*512 + x;
    float a0 = Gb[0], a1 = Gb[IMN], a2 = Gb[2*IMN];
    const float inv3  = 1.0f/3.0f;
    const float invKK = 1.0f/(0.03f*0.03f);
    if (y < 511) {
        float m = (fabsf(Gb[512]-a0) + fabsf(Gb[IMN+512]-a1) + fabsf(Gb[2*IMN+512]-a2)) * inv3;
        g_cv[b*CVN + y*512 + x] = 1.0f/(1.0f + m*m*invKK);
    }
    if (x < 511) {
        float m = (fabsf(Gb[1]-a0) + fabsf(Gb[IMN+1]-a1) + fabsf(Gb[2*IMN+1]-a2)) * inv3;
        g_ch[b*CHN + y*511 + x] = 1.0f/(1.0f + m*m*invKK);
    }
}

__global__ void k_ur()
{
    int idx = blockIdx.x*blockDim.x + threadIdx.x;
    if (idx >= NB*URN) return;
    int b = idx / URN;
    int r = idx - b*URN;
    int y = r / 511;
    int x = r - y*511;
    const float* cvb = g_cv + b*CVN;
    const float* chb = g_ch + b*CHN;
    float s1=0.f, s2=0.f, t1=0.f, t2=0.f;
    #pragma unroll
    for (int dy=-1; dy<=1; ++dy) {
        int yy = y + dy;
        #pragma unroll
        for (int dx=-1; dx<=1; ++dx) {
            int xx = x + dx;
            if (yy >= 0 && yy < 511 && xx >= 0 && xx < 512) {
                float v = cvb[yy*512 + xx]; s1 += v; s2 += v*v;
            }
            if (yy >= 0 && yy < 512 && xx >= 0 && xx < 511) {
                float v = chb[yy*511 + xx]; t1 += v; t2 += v*v;
            }
        }
    }
    const float i9 = 1.0f/9.0f;
    float av = s1*i9, av2 = s2*i9;
    float bv = t1*i9, bv2 = t2*i9;
    g_ur[idx] = ((av2 - av*av) < 0.1f && (bv2 - bv*bv) < 0.1f) ? 1 : 0;
}

// ---------------------------------------------------------------- phase 3 ---
// One CTA per (batch, tile); tile ping-pong entirely in dynamic smem.
// Wave w = 2i + j: earlier-order overlapping tiles have smaller wave;
// same-wave tiles are spatially disjoint.
__global__ void __launch_bounds__(1024) k_fft(int w, int i0)
{
    extern __shared__ float dynbuf[];          // 2 x 16384 floats
    __shared__ float red[96];
    __shared__ float coef[4];

    int b  = blockIdx.x & 1;
    int t  = blockIdx.x >> 1;
    int i  = i0 + t;
    int j  = w - 2*i;
    int ty = 112*i, tx = 112*j;
    int h  = min(128, 512 - ty);
    int ww = min(128, 512 - tx);
    int tid = threadIdx.x;

    const float*         cvb = g_cv + b*CVN;
    const float*         chb = g_ch + b*CHN;
    const unsigned char* urb = g_ur + b*URN;
    float*               Db  = g_depth + b*IMN;

    // block means over reference slice shapes
    float s_cv = 0.f, s_ch = 0.f, s_ur = 0.f;
    int rh = h - 1;
    for (int k = tid; k < rh*ww; k += 1024) {
        int r = k / ww, c = k - r*ww;
        s_cv += cvb[(ty + r)*512 + tx + c];
    }
    int cw = ww - 1;
    for (int k = tid; k < h*cw; k += 1024) {
        int r = k / cw, c = k - r*cw;
        s_ch += chb[(ty + r)*511 + tx + c];
    }
    int uh = min(ty + h, 511) - ty;
    int uw = min(tx + ww, 511) - tx;
    for (int k = tid; k < uh*uw; k += 1024) {
        int r = k / uw, c = k - r*uw;
        s_ur += (float)urb[(ty + r)*511 + tx + c];
    }
    unsigned lane = tid & 31, wi = tid >> 5;
    for (int o = 16; o; o >>= 1) {
        s_cv += __shfl_down_sync(0xffffffffu, s_cv, o);
        s_ch += __shfl_down_sync(0xffffffffu, s_ch, o);
        s_ur += __shfl_down_sync(0xffffffffu, s_ur, o);
    }
    if (lane == 0) { red[wi] = s_cv; red[32+wi] = s_ch; red[64+wi] = s_ur; }
    __syncthreads();
    if (tid == 0) {
        float a = 0.f, bb = 0.f, u = 0.f;
        for (int k = 0; k < 32; ++k) { a += red[k]; bb += red[32+k]; u += red[64+k]; }
        float cvm  = a  / (float)(rh*ww);
        float chm  = bb / (float)(h*cw);
        float unif = u  / (float)(uh*uw);
        float A = LDIFF*cvm, B = LDIFF*chm;
        coef[0] = 1.0f - 2.0f*A - 2.0f*B;
        coef[1] = A; coef[2] = B; coef[3] = unif;
    }
    __syncthreads();
    float c0 = coef[0], A = coef[1], B = coef[2];
    bool  doit = coef[3] > 0.7f;

    // load tile into smem (row stride 128 floats)
    float* bufA = dynbuf;
    float* bufB = dynbuf + 16384;
    int wsh = (ww == 128) ? 7 : 6;
    int npts = h*ww;
    for (int k = tid; k < npts; k += 1024) {
        int r = k >> wsh, c = k & (ww-1);
        bufA[(r<<7) + c] = Db[(ty + r)*512 + tx + c];
    }
    __syncthreads();

    // 10 circular 5-pt stencil steps == irfft2(rfft2(x) * op^10)
    float* src = bufA;
    float* dst = bufB;
    int qs = (ww == 128) ? 5 : 4;       // log2(ww/4)
    int wq = ww >> 2;
    int npts4 = h * wq;
    for (int it = 0; it < 10; ++it) {
        for (int k = tid; k < npts4; k += 1024) {
            int r  = k >> qs;
            int c4 = (k & (wq-1)) << 2;
            int ru = (r == 0)    ? h-1 : r-1;
            int rd = (r == h-1)  ? 0   : r+1;
            float4 ce = *(const float4*)(src + (r <<7) + c4);
            float4 up = *(const float4*)(src + (ru<<7) + c4);
            float4 dn = *(const float4*)(src + (rd<<7) + c4);
            float  lf = src[(r<<7) + ((c4 == 0)      ? ww-1 : c4-1)];
            float  rt = src[(r<<7) + ((c4 + 4 == ww) ? 0    : c4+4)];
            float4 o;
            o.x = c0*ce.x + A*(up.x + dn.x) + B*(lf   + ce.y);
            o.y = c0*ce.y + A*(up.y + dn.y) + B*(ce.x + ce.z);
            o.z = c0*ce.z + A*(up.z + dn.z) + B*(ce.y + ce.w);
            o.w = c0*ce.w + A*(up.w + dn.w) + B*(ce.z + rt);
            *(float4*)(dst + (r<<7) + c4) = o;
        }
        __syncthreads();
        float* tmp = src; src = dst; dst = tmp;
    }

    // blend + conditional commit
    for (int k = tid; k < npts; k += 1024) {
        int r = k >> wsh, c = k & (ww-1);
        int gi = (ty + r)*512 + tx + c;
        float oldv = Db[gi];
        float newv = src[(r<<7) + c];
        float by = (ty > 0 && r < 16) ? (float)r * (1.0f/16.0f) : 1.0f;
        float bx = (tx > 0 && c < 16) ? (float)c * (1.0f/16.0f) : 1.0f;
        float bl = by * bx;
        float cand = oldv*(1.0f - bl) + newv*bl;
        Db[gi] = doit ? cand : oldv;
    }
}

// ---------------------------------------------------------------- phase 4 ---
// 10 fused stencil iterations per launch (25 x 10 = 250). 64x64 output tile,
// 84x84 halo tile in dynamic-smem ping-pong (2 x 84 x 86 x 4 = 57.8 KB).
// Per-thread fixed ownership of <=7 points; flux coefficients preloaded into
// registers once (pre-scaled by L; zeroed where the flux doesn't exist ->
// bit-identical to guarded arithmetic). Iteration it writes [it+1, HT-2-it]^2,
// exactly the region iteration it+1 reads; after 10 iters the window [10,73]
// equals the output region. Final launch writes d_out directly.
#define FUSE 10
#define TS   64
#define HT   (TS + 2*FUSE)   // 84
#define PADW (HT + 2)        // 86
#define NTH  1024
#define NPT  ((HT*HT + NTH - 1)/NTH)   // 7

__global__ void __launch_bounds__(NTH) k_iter(int parity, float* fout)
{
    extern __shared__ float dynbuf[];          // 2 x HT*PADW floats
    const float* I = (parity ? g_depth2 : g_depth)  + blockIdx.z*IMN;
    float*       O = (parity ? g_depth  : g_depth2) + blockIdx.z*IMN;
    const float* cvb = g_cv + blockIdx.z*CVN;
    const float* chb = g_ch + blockIdx.z*CHN;
    int y0 = blockIdx.y*TS - FUSE;
    int x0 = blockIdx.x*TS - FUSE;

    float* sA = dynbuf;
    float* sB = dynbuf + HT*PADW;
    int tid = threadIdx.x;

    // preload field into smem + flux coefficients into registers
    float cvd[NPT], cvu[NPT], chr[NPT], chl[NPT];
    #pragma unroll
    for (int i = 0; i < NPT; ++i) {
        int k = tid + i*NTH;
        float a = 0.f, b = 0.f, cR = 0.f, cL = 0.f;
        if (k < HT*HT) {
            int r = k / HT, c = k - (k / HT)*HT;
            int y = y0 + r, x = x0 + c;
            float v = 0.0f;
            if ((unsigned)y < 512u && (unsigned)x < 512u) {
                v = I[y*512 + x];
                if (y < 511) a  = LDIFF * cvb[y*512 + x];
                if (y > 0)   b  = LDIFF * cvb[(y-1)*512 + x];
                if (x < 511) cR = LDIFF * chb[y*511 + x];
                if (x > 0)   cL = LDIFF * chb[y*511 + x - 1];
            }
            sA[r*PADW + c] = v;
        }
        cvd[i] = a; cvu[i] = b; chr[i] = cR; chl[i] = cL;
    }
    __syncthreads();

    float* src = sA;
    float* dst = sB;
    #pragma unroll 1
    for (int it = 0; it < FUSE; ++it) {
        int lo = it + 1;
        int hi = HT - 2 - it;
        #pragma unroll
        for (int i = 0; i < NPT; ++i) {
            int k = tid + i*NTH;
            int r = k / HT, c = k - (k / HT)*HT;   // HT constant -> mul/shift
            if (k < HT*HT && r >= lo && r <= hi && c >= lo && c <= hi) {
                float cen = src[r*PADW + c];
                float acc = cen
                    + cvd[i] * (src[(r+1)*PADW + c] - cen)
                    - cvu[i] * (cen - src[(r-1)*PADW + c])
                    + chr[i] * (src[r*PADW + c + 1] - cen)
                    - chl[i] * (cen - src[r*PADW + c - 1]);
                dst[r*PADW + c] = acc;
            }
        }
        __syncthreads();
        float* t = src; src = dst; dst = t;
    }

    float* Ob = fout ? (fout + blockIdx.z*IMN) : O;
    for (int k = tid; k < TS*TS; k += NTH) {
        int r = k >> 6, c = k & 63;
        int y = y0 + FUSE + r, x = x0 + FUSE + c;
        Ob[y*512 + x] = src[(r+FUSE)*PADW + (c+FUSE)];
    }
}

// ---------------------------------------------------------------------------
#define FFT_SMEM  (2*16384*4)            // 131072 B
#define ITER_SMEM (2*HT*PADW*4)          // 57792 B

extern "C" void kernel_launch(void* const* d_in, const int* in_sizes, int n_in,
                              void* d_out, int out_size)
{
    const float* guide   = (const float*)d_in[0];
    const float* initial = (const float*)d_in[1];
    float*       out     = (float*)d_out;

    // raise dynamic-smem caps (host-side attribute set; no allocation)
    cudaFuncSetAttribute(k_fft,  cudaFuncAttributeMaxDynamicSharedMemorySize, FFT_SMEM);
    cudaFuncSetAttribute(k_iter, cudaFuncAttributeMaxDynamicSharedMemorySize, ITER_SMEM);

    k_cvch<<<2048, 256>>>(guide);
    k_ur  <<<(NB*URN + 255)/256, 256>>>();

    // seed depth = initial (shift eliminated by linearity; see header)
    void* depth_ptr = nullptr;
    cudaGetSymbolAddress(&depth_ptr, g_depth);
    cudaMemcpyAsync(depth_ptr, initial, NB*IMN*sizeof(float),
                    cudaMemcpyDeviceToDevice);

    for (int w = 0; w < 13; ++w) {
        int i_min = (w - 3) / 2; if (i_min < 0) i_min = 0;
        int i_max = w / 2;       if (i_max > 4) i_max = 4;
        int nt = i_max - i_min + 1;
        k_fft<<<nt*2, 1024, FFT_SMEM>>>(w, i_min);
    }

    // 25 launches x 10 iters = 250; final launch writes d_out directly.
    for (int f = 0; f < 25; ++f)
        k_iter<<<dim3(8, 8, NB), NTH, ITER_SMEM>>>(f & 1, (f == 24) ? out : nullptr);
}